// round 3
// baseline (speedup 1.0000x reference)
#include <cuda_runtime.h>
#include <cstdint>

// 16-byte device state: { double acc; unsigned long long count; }
// Zeroed each call by a cudaMemsetAsync node (graph-capturable, no alloc).
struct State { double acc; unsigned long long count; };
__device__ State g_state;

// One warp per row. C=1000 floats = 250 float4 (row stride 4000B, 16B-aligned).
// Front-batched loads: 7 unconditional float4 per lane + 1 predicated tail
// (7*32 + 26 = 250) -> 8 independent loads in flight per lane before any FMA.
__global__ __launch_bounds__(256)
void cosine_loss_kernel(const float* __restrict__ logits,
                        const int* __restrict__ labels,
                        int N, int C, float* __restrict__ out, double inv_n) {
    const int gwarp = (blockIdx.x * blockDim.x + threadIdx.x) >> 5;
    const int lane  = threadIdx.x & 31;
    const int warp_in_block = threadIdx.x >> 5;

    double local = 0.0;

    if (gwarp < N) {
        const size_t row_off = (size_t)gwarp * (size_t)C;
        const float4* __restrict__ row4 = reinterpret_cast<const float4*>(logits + row_off);

        // Batch all loads first (max MLP), streaming hint (read-once data).
        float4 v[8];
        #pragma unroll
        for (int k = 0; k < 7; k++)
            v[k] = __ldcs(row4 + lane + 32 * k);
        v[7] = make_float4(0.f, 0.f, 0.f, 0.f);
        if (lane < 26)                       // 224 + 26 = 250 float4s
            v[7] = __ldcs(row4 + lane + 224);

        float s = 0.0f;
        #pragma unroll
        for (int k = 0; k < 8; k++) {
            s = fmaf(v[k].x, v[k].x, s);
            s = fmaf(v[k].y, v[k].y, s);
            s = fmaf(v[k].z, v[k].z, s);
            s = fmaf(v[k].w, v[k].w, s);
        }
        #pragma unroll
        for (int o = 16; o > 0; o >>= 1)
            s += __shfl_xor_sync(0xFFFFFFFFu, s, o);

        if (lane == 0) {
            const int lab = __ldg(labels + gwarp);
            const float dot = __ldg(logits + row_off + (size_t)lab);
            const float norm = sqrtf(s);
            const float cosv = dot / fmaxf(norm, 1e-8f);
            local = 1.0 - (double)cosv;
        }
    }

    // Block reduction (8 warps) -> one double atomic per block.
    __shared__ double sh[8];
    if (lane == 0) sh[warp_in_block] = local;
    __syncthreads();

    if (threadIdx.x == 0) {
        double t = 0.0;
        #pragma unroll
        for (int i = 0; i < 8; i++) t += sh[i];
        atomicAdd(&g_state.acc, t);

        // Last block to arrive finalizes the mean into d_out.
        __threadfence();
        unsigned long long ticket = atomicAdd(&g_state.count, 1ULL);
        if (ticket == (unsigned long long)gridDim.x - 1ULL) {
            double acc = *(volatile double*)&g_state.acc;
            *out = (float)(acc * inv_n);
        }
    }
}

extern "C" void kernel_launch(void* const* d_in, const int* in_sizes, int n_in,
                              void* d_out, int out_size) {
    const float* logits = (const float*)d_in[0];
    const int*   labels = (const int*)d_in[1];
    float* out = (float*)d_out;

    const int N = in_sizes[1];          // rows == labels
    const int C = in_sizes[0] / N;      // 1000

    // Zero the accumulator + ticket counter (graph-capturable memset node).
    void* state_ptr = nullptr;
    cudaGetSymbolAddress(&state_ptr, g_state);
    cudaMemsetAsync(state_ptr, 0, sizeof(State), 0);

    const int threads = 256;            // 8 warps/block -> 8 rows/block
    const int blocks = (N * 32 + threads - 1) / threads;
    cosine_loss_kernel<<<blocks, threads>>>(logits, labels, N, C, out,
                                            1.0 / (double)N);
}

// round 4
// speedup vs baseline: 1.2079x; 1.2079x over previous
#include <cuda_runtime.h>
#include <cstdint>

// Device state: { double acc; unsigned long long count; } — zeroed by a
// cudaMemsetAsync graph node each call.
struct State { double acc; unsigned long long count; };
__device__ State g_state;

static constexpr int BLOCKS  = 1184;   // 8 blocks per SM on 148 SMs
static constexpr int THREADS = 256;    // 8 warps/block

// Persistent warps: each warp grid-strides over rows. Per row:
//  - lane 0 issues label + gather loads FIRST (their latency overlaps the row
//    stream; value consumed only after the reduction),
//  - 8 batched float4 streaming loads per lane cover C=1000 floats,
//  - warp shuffle-reduce sum of squares, lane 0 accumulates 1 - cos in double.
// One shared reduce + one global atomic per block at the very end.
__global__ __launch_bounds__(THREADS)
void cosine_loss_kernel(const float* __restrict__ logits,
                        const int* __restrict__ labels,
                        int N, int C, float* __restrict__ out, double inv_n) {
    const int lane  = threadIdx.x & 31;
    const int warp_in_block = threadIdx.x >> 5;
    const int gwarp = blockIdx.x * (THREADS >> 5) + warp_in_block;
    const int total_warps = BLOCKS * (THREADS >> 5);

    double local = 0.0;

    for (int row = gwarp; row < N; row += total_warps) {
        const size_t row_off = (size_t)row * (size_t)C;
        const float4* __restrict__ row4 =
            reinterpret_cast<const float4*>(logits + row_off);

        // Issue the dependent gather chain early (lane 0 only).
        float dot = 0.0f;
        if (lane == 0) {
            const int lab = __ldg(labels + row);
            dot = __ldg(logits + row_off + (size_t)lab);
        }

        // Batched streaming loads: 7 full + 1 predicated (224 + 26 = 250).
        float4 v[8];
        #pragma unroll
        for (int k = 0; k < 7; k++)
            v[k] = __ldcs(row4 + lane + 32 * k);
        v[7] = make_float4(0.f, 0.f, 0.f, 0.f);
        if (lane < 26)
            v[7] = __ldcs(row4 + lane + 224);

        float s = 0.0f;
        #pragma unroll
        for (int k = 0; k < 8; k++) {
            s = fmaf(v[k].x, v[k].x, s);
            s = fmaf(v[k].y, v[k].y, s);
            s = fmaf(v[k].z, v[k].z, s);
            s = fmaf(v[k].w, v[k].w, s);
        }
        #pragma unroll
        for (int o = 16; o > 0; o >>= 1)
            s += __shfl_xor_sync(0xFFFFFFFFu, s, o);

        if (lane == 0) {
            const float cosv = dot / fmaxf(sqrtf(s), 1e-8f);
            local += 1.0 - (double)cosv;
        }
    }

    // Block reduction (once per block, not per row).
    __shared__ double sh[THREADS >> 5];
    if (lane == 0) sh[warp_in_block] = local;
    __syncthreads();

    if (threadIdx.x == 0) {
        double t = 0.0;
        #pragma unroll
        for (int i = 0; i < (THREADS >> 5); i++) t += sh[i];
        atomicAdd(&g_state.acc, t);

        __threadfence();
        unsigned long long ticket = atomicAdd(&g_state.count, 1ULL);
        if (ticket == (unsigned long long)gridDim.x - 1ULL) {
            double acc = *(volatile double*)&g_state.acc;
            *out = (float)(acc * inv_n);
        }
    }
}

extern "C" void kernel_launch(void* const* d_in, const int* in_sizes, int n_in,
                              void* d_out, int out_size) {
    const float* logits = (const float*)d_in[0];
    const int*   labels = (const int*)d_in[1];
    float* out = (float*)d_out;

    const int N = in_sizes[1];          // rows == labels
    const int C = in_sizes[0] / N;      // 1000

    void* state_ptr = nullptr;
    cudaGetSymbolAddress(&state_ptr, g_state);
    cudaMemsetAsync(state_ptr, 0, sizeof(State), 0);

    cosine_loss_kernel<<<BLOCKS, THREADS>>>(logits, labels, N, C, out,
                                            1.0 / (double)N);
}

// round 5
// speedup vs baseline: 1.2405x; 1.0270x over previous
#include <cuda_runtime.h>
#include <cstdint>

struct State { double acc; unsigned long long count; };
__device__ State g_state;

static constexpr int BLOCKS  = 1184;   // 8 blocks per SM on 148 SMs (occ may be reg-limited; fine)
static constexpr int THREADS = 256;    // 8 warps/block
static constexpr int WARPS_TOTAL = BLOCKS * (THREADS / 32);

// Software-pipelined persistent warps: while reducing row k, row k+1's
// 8 float4 loads + label gather are already in flight. The per-row reduce
// tail (FMA + 5 SHFL + sqrt) is fully hidden behind memory.
__global__ __launch_bounds__(THREADS)
void cosine_loss_kernel(const float* __restrict__ logits,
                        const int* __restrict__ labels,
                        int N, int C, float* __restrict__ out, double inv_n) {
    const int lane  = threadIdx.x & 31;
    const int warp_in_block = threadIdx.x >> 5;
    const int gwarp = blockIdx.x * (THREADS >> 5) + warp_in_block;

    double local = 0.0;

    int row = gwarp;
    float4 v[8];
    float dot = 0.0f;

    // Prologue: issue loads for the first row.
    if (row < N) {
        const size_t row_off = (size_t)row * (size_t)C;
        const float4* __restrict__ row4 =
            reinterpret_cast<const float4*>(logits + row_off);
        if (lane == 0) {
            const int lab = __ldg(labels + row);
            dot = __ldg(logits + row_off + (size_t)lab);
        }
        #pragma unroll
        for (int k = 0; k < 7; k++)
            v[k] = __ldcs(row4 + lane + 32 * k);
        v[7] = make_float4(0.f, 0.f, 0.f, 0.f);
        if (lane < 26)
            v[7] = __ldcs(row4 + lane + 224);
    }

    while (row < N) {
        // Snapshot current row's data, then immediately issue next row's loads.
        float4 cur[8];
        #pragma unroll
        for (int k = 0; k < 8; k++) cur[k] = v[k];
        const float dotc = dot;

        const int next = row + WARPS_TOTAL;
        if (next < N) {
            const size_t row_off = (size_t)next * (size_t)C;
            const float4* __restrict__ row4 =
                reinterpret_cast<const float4*>(logits + row_off);
            if (lane == 0) {
                const int lab = __ldg(labels + next);
                dot = __ldg(logits + row_off + (size_t)lab);
            }
            #pragma unroll
            for (int k = 0; k < 7; k++)
                v[k] = __ldcs(row4 + lane + 32 * k);
            v[7] = make_float4(0.f, 0.f, 0.f, 0.f);
            if (lane < 26)
                v[7] = __ldcs(row4 + lane + 224);
        }

        // Reduce the current row (overlapped with next row's loads).
        float s = 0.0f;
        #pragma unroll
        for (int k = 0; k < 8; k++) {
            s = fmaf(cur[k].x, cur[k].x, s);
            s = fmaf(cur[k].y, cur[k].y, s);
            s = fmaf(cur[k].z, cur[k].z, s);
            s = fmaf(cur[k].w, cur[k].w, s);
        }
        #pragma unroll
        for (int o = 16; o > 0; o >>= 1)
            s += __shfl_xor_sync(0xFFFFFFFFu, s, o);

        if (lane == 0) {
            const float cosv = dotc / fmaxf(sqrtf(s), 1e-8f);
            local += 1.0 - (double)cosv;
        }

        row = next;
    }

    // Block reduction, once per block.
    __shared__ double sh[THREADS >> 5];
    if (lane == 0) sh[warp_in_block] = local;
    __syncthreads();

    if (threadIdx.x == 0) {
        double t = 0.0;
        #pragma unroll
        for (int i = 0; i < (THREADS >> 5); i++) t += sh[i];
        atomicAdd(&g_state.acc, t);

        __threadfence();
        unsigned long long ticket = atomicAdd(&g_state.count, 1ULL);
        if (ticket == (unsigned long long)gridDim.x - 1ULL) {
            double acc = *(volatile double*)&g_state.acc;
            *out = (float)(acc * inv_n);
        }
    }
}

extern "C" void kernel_launch(void* const* d_in, const int* in_sizes, int n_in,
                              void* d_out, int out_size) {
    const float* logits = (const float*)d_in[0];
    const int*   labels = (const int*)d_in[1];
    float* out = (float*)d_out;

    const int N = in_sizes[1];          // rows == labels
    const int C = in_sizes[0] / N;      // 1000

    void* state_ptr = nullptr;
    cudaGetSymbolAddress(&state_ptr, g_state);
    cudaMemsetAsync(state_ptr, 0, sizeof(State), 0);

    cosine_loss_kernel<<<BLOCKS, THREADS>>>(logits, labels, N, C, out,
                                            1.0 / (double)N);
}